// round 1
// baseline (speedup 1.0000x reference)
#include <cuda_runtime.h>
#include <cuda_bf16.h>
#include <cstdint>

// Problem constants (fixed by the dataset)
#define BB   4096
#define DZ   512
#define HH   2048
#define DY   10
#define NSTEPS 64

// Scratch (allocation-free rule: __device__ globals)
__device__ float g_M0[DZ * DZ];
__device__ float g_M1[DZ * DZ];
__device__ float g_W1eff[HH * DZ];
__device__ float g_H[(size_t)BB * HH];

// ---------------------------------------------------------------------------
// build M = I + dt * A^T   (M[i][j] = (i==j) + dt*A[j][i])
// ---------------------------------------------------------------------------
__global__ void build_M_kernel(const float* __restrict__ A, float* __restrict__ M, float dt) {
    int j = blockIdx.x * blockDim.x + threadIdx.x;
    int i = blockIdx.y * blockDim.y + threadIdx.y;
    if (i < DZ && j < DZ) {
        float v = dt * A[(size_t)j * DZ + i];
        if (i == j) v += 1.0f;
        M[(size_t)i * DZ + j] = v;
    }
}

// ---------------------------------------------------------------------------
// Generic tiled SGEMM.
//   TRANSB=true :  C[m][n] = sum_k A[m][k] * B[n][k]   (B is N x K, row-major)
//   TRANSB=false:  C[m][n] = sum_k A[m][k] * B[k][n]   (B is K x N, row-major)
// Optional bias[n] add and ReLU in epilogue.
// Requires M%BM==0, N%BN==0, K%BK==0, K%4==0 (all satisfied here).
// ---------------------------------------------------------------------------
template <int BM, int BN, int BK, int TM, int TN, bool TRANSB, bool RELU, bool BIAS>
__global__ void __launch_bounds__((BM / TM) * (BN / TN))
sgemm_kernel(const float* __restrict__ A, const float* __restrict__ B,
             const float* __restrict__ bias, float* __restrict__ C,
             int M, int N, int K) {
    constexpr int THREADS = (BM / TM) * (BN / TN);
    const int tid = threadIdx.x;
    const int tx  = tid % (BN / TN);
    const int ty  = tid / (BN / TN);
    const int bm0 = blockIdx.y * BM;
    const int bn0 = blockIdx.x * BN;

    __shared__ float As[BK][BM];
    __shared__ float Bs[BK][BN];

    float acc[TM][TN];
#pragma unroll
    for (int m = 0; m < TM; m++)
#pragma unroll
        for (int n = 0; n < TN; n++) acc[m][n] = 0.0f;

    for (int k0 = 0; k0 < K; k0 += BK) {
        // --- load A tile (BM x BK), vectorized along K, store transposed ---
        constexpr int A_VECS = BM * BK / 4;
#pragma unroll
        for (int i = tid; i < A_VECS; i += THREADS) {
            int r  = i / (BK / 4);
            int c4 = i % (BK / 4);
            float4 v = *reinterpret_cast<const float4*>(
                &A[(size_t)(bm0 + r) * K + k0 + c4 * 4]);
            As[c4 * 4 + 0][r] = v.x;
            As[c4 * 4 + 1][r] = v.y;
            As[c4 * 4 + 2][r] = v.z;
            As[c4 * 4 + 3][r] = v.w;
        }
        // --- load B tile ---
        if (TRANSB) {
            constexpr int B_VECS = BN * BK / 4;
#pragma unroll
            for (int i = tid; i < B_VECS; i += THREADS) {
                int r  = i / (BK / 4);
                int c4 = i % (BK / 4);
                float4 v = *reinterpret_cast<const float4*>(
                    &B[(size_t)(bn0 + r) * K + k0 + c4 * 4]);
                Bs[c4 * 4 + 0][r] = v.x;
                Bs[c4 * 4 + 1][r] = v.y;
                Bs[c4 * 4 + 2][r] = v.z;
                Bs[c4 * 4 + 3][r] = v.w;
            }
        } else {
            constexpr int B_VECS = BK * BN / 4;
#pragma unroll
            for (int i = tid; i < B_VECS; i += THREADS) {
                int r  = i / (BN / 4);
                int c4 = i % (BN / 4);
                float4 v = *reinterpret_cast<const float4*>(
                    &B[(size_t)(k0 + r) * N + bn0 + c4 * 4]);
                *reinterpret_cast<float4*>(&Bs[r][c4 * 4]) = v;
            }
        }
        __syncthreads();

#pragma unroll
        for (int kk = 0; kk < BK; ++kk) {
            float a[TM], b[TN];
#pragma unroll
            for (int m = 0; m < TM; m++) a[m] = As[kk][ty * TM + m];
#pragma unroll
            for (int n = 0; n < TN; n++) b[n] = Bs[kk][tx * TN + n];
#pragma unroll
            for (int m = 0; m < TM; m++)
#pragma unroll
                for (int n = 0; n < TN; n++)
                    acc[m][n] = fmaf(a[m], b[n], acc[m][n]);
        }
        __syncthreads();
    }

    // --- epilogue ---
#pragma unroll
    for (int m = 0; m < TM; m++) {
        int row = bm0 + ty * TM + m;
#pragma unroll
        for (int n = 0; n < TN; n++) {
            int col = bn0 + tx * TN + n;
            float v = acc[m][n];
            if (BIAS) v += bias[col];
            if (RELU) v = fmaxf(v, 0.0f);
            C[(size_t)row * N + col] = v;
        }
    }
}

// ---------------------------------------------------------------------------
// Final layer: y[b][d] = sum_h H[b][h] * W2[d][h] + b2[d]   (DY=10, H=2048)
// One block per batch row, warp-shuffle + smem reduction.
// ---------------------------------------------------------------------------
__global__ void __launch_bounds__(256)
final_layer_kernel(const float* __restrict__ Hbuf, const float* __restrict__ W2,
                   const float* __restrict__ b2, float* __restrict__ y) {
    int b = blockIdx.x;
    const float* hr = Hbuf + (size_t)b * HH;

    float acc[DY];
#pragma unroll
    for (int d = 0; d < DY; d++) acc[d] = 0.0f;

    for (int hh = threadIdx.x; hh < HH; hh += 256) {
        float hv = hr[hh];
#pragma unroll
        for (int d = 0; d < DY; d++)
            acc[d] = fmaf(hv, W2[(size_t)d * HH + hh], acc[d]);
    }

    // warp reduction
#pragma unroll
    for (int off = 16; off > 0; off >>= 1)
#pragma unroll
        for (int d = 0; d < DY; d++)
            acc[d] += __shfl_xor_sync(0xFFFFFFFFu, acc[d], off);

    __shared__ float red[8][DY];
    int w = threadIdx.x >> 5, l = threadIdx.x & 31;
    if (l == 0)
#pragma unroll
        for (int d = 0; d < DY; d++) red[w][d] = acc[d];
    __syncthreads();

    if (threadIdx.x < DY) {
        float s = b2[threadIdx.x];
#pragma unroll
        for (int ww = 0; ww < 8; ww++) s += red[ww][threadIdx.x];
        y[(size_t)b * DY + threadIdx.x] = s;
    }
}

// ---------------------------------------------------------------------------
// Launch
// ---------------------------------------------------------------------------
extern "C" void kernel_launch(void* const* d_in, const int* in_sizes, int n_in,
                              void* d_out, int out_size) {
    const float* x  = (const float*)d_in[0];
    const float* A  = (const float*)d_in[1];
    const float* W1 = (const float*)d_in[2];
    const float* b1 = (const float*)d_in[3];
    const float* W2 = (const float*)d_in[4];
    const float* b2 = (const float*)d_in[5];
    float* y = (float*)d_out;

    float *M0, *M1, *W1eff, *Hbuf;
    cudaGetSymbolAddress((void**)&M0, g_M0);
    cudaGetSymbolAddress((void**)&M1, g_M1);
    cudaGetSymbolAddress((void**)&W1eff, g_W1eff);
    cudaGetSymbolAddress((void**)&Hbuf, g_H);

    // 1) M = I + dt * A^T
    {
        dim3 blk(16, 16), grd(DZ / 16, DZ / 16);
        build_M_kernel<<<grd, blk>>>(A, M0, 1.0f / (float)NSTEPS);
    }

    // 2) M^64 via 6 squarings (NN gemm, 512^3 each), ping-pong M0<->M1
    float* src = M0;
    float* dst = M1;
    for (int s = 0; s < 6; ++s) {
        dim3 grd(DZ / 64, DZ / 64);
        sgemm_kernel<64, 64, 16, 4, 4, /*TRANSB=*/false, false, false>
            <<<grd, 256>>>(src, src, nullptr, dst, DZ, DZ, DZ);
        float* t = src; src = dst; dst = t;
    }
    // result (M^64) now in src

    // 3) W1eff = W1 @ (M^64)^T   — NT gemm: C[h][i] = sum_j W1[h][j] * M64[i][j]
    {
        dim3 grd(DZ / 64, HH / 64);
        sgemm_kernel<64, 64, 16, 4, 4, /*TRANSB=*/true, false, false>
            <<<grd, 256>>>(W1, src, nullptr, W1eff, HH, DZ, DZ);
    }

    // 4) H = relu(x @ W1eff^T + b1)  — the big one: 4096 x 2048 x 512
    {
        dim3 grd(HH / 128, BB / 128);
        sgemm_kernel<128, 128, 16, 8, 8, /*TRANSB=*/true, /*RELU=*/true, /*BIAS=*/true>
            <<<grd, 256>>>(x, W1eff, b1, Hbuf, BB, HH, DZ);
    }

    // 5) y = H @ W2^T + b2
    final_layer_kernel<<<BB, 256>>>(Hbuf, W2, b2, y);
}

// round 2
// speedup vs baseline: 1.3581x; 1.3581x over previous
#include <cuda_runtime.h>
#include <cuda_bf16.h>
#include <cstdint>

// Problem constants (fixed by the dataset)
#define BB   4096
#define DZ   512
#define HH   2048
#define DY   10
#define NSTEPS 64
#define KSPLITS 4

// Scratch (allocation-free rule: __device__ globals)
__device__ float g_M0[DZ * DZ];
__device__ float g_M1[DZ * DZ];
__device__ float g_Part[KSPLITS * DZ * DZ];
__device__ float g_W1eff[HH * DZ];
__device__ float g_H[(size_t)BB * HH];

// ---------------------------------------------------------------------------
// build M = I + dt * A^T   (M[i][j] = (i==j) + dt*A[j][i])
// ---------------------------------------------------------------------------
__global__ void build_M_kernel(const float* __restrict__ A, float* __restrict__ M, float dt) {
    int j = blockIdx.x * blockDim.x + threadIdx.x;
    int i = blockIdx.y * blockDim.y + threadIdx.y;
    if (i < DZ && j < DZ) {
        float v = dt * A[(size_t)j * DZ + i];
        if (i == j) v += 1.0f;
        M[(size_t)i * DZ + j] = v;
    }
}

// ---------------------------------------------------------------------------
// Tiled SGEMM with register prefetch (double-buffer via regs).
//   TRANSB=true :  C[m][n] = sum_k A[m][k] * B[n][k]
//   TRANSB=false:  C[m][n] = sum_k A[m][k] * B[k][n]
//   SPLITK=true :  blockIdx.z selects K slice [z*Ksplit, (z+1)*Ksplit),
//                  output goes to C + z*M*N (partials, reduced later).
// Requires M%BM==0, N%BN==0, K%BK==0, TN%4==0, TM%4==0.
// ---------------------------------------------------------------------------
template <int BM, int BN, int BK, int TM, int TN, bool TRANSB, bool RELU, bool BIAS, bool SPLITK>
__global__ void __launch_bounds__((BM / TM) * (BN / TN))
sgemm2(const float* __restrict__ A, const float* __restrict__ B,
       const float* __restrict__ bias, float* __restrict__ C,
       int M, int N, int K, int Ksplit) {
    constexpr int THREADS = (BM / TM) * (BN / TN);
    constexpr int AV = BM * BK / (4 * THREADS);
    constexpr int BV = BN * BK / (4 * THREADS);   // same count either layout
    const int tid = threadIdx.x;
    const int tx  = tid % (BN / TN);
    const int ty  = tid / (BN / TN);
    const int bm0 = blockIdx.y * BM;
    const int bn0 = blockIdx.x * BN;

    int kbeg = 0, kend = K;
    if (SPLITK) {
        kbeg = blockIdx.z * Ksplit;
        kend = kbeg + Ksplit;
        C += (size_t)blockIdx.z * M * N;
    }

    __shared__ float As[BK][BM];
    __shared__ float Bs[BK][BN];

    float acc[TM][TN];
#pragma unroll
    for (int m = 0; m < TM; m++)
#pragma unroll
        for (int n = 0; n < TN; n++) acc[m][n] = 0.0f;

    float4 pa[AV], pb[BV];

    auto loadA = [&](int k0) {
#pragma unroll
        for (int v = 0; v < AV; v++) {
            int idx = tid + v * THREADS;
            int r = idx / (BK / 4), c4 = idx % (BK / 4);
            pa[v] = *reinterpret_cast<const float4*>(&A[(size_t)(bm0 + r) * K + k0 + c4 * 4]);
        }
    };
    auto storeA = [&]() {
#pragma unroll
        for (int v = 0; v < AV; v++) {
            int idx = tid + v * THREADS;
            int r = idx / (BK / 4), c4 = idx % (BK / 4);
            As[c4 * 4 + 0][r] = pa[v].x;
            As[c4 * 4 + 1][r] = pa[v].y;
            As[c4 * 4 + 2][r] = pa[v].z;
            As[c4 * 4 + 3][r] = pa[v].w;
        }
    };
    auto loadB = [&](int k0) {
#pragma unroll
        for (int v = 0; v < BV; v++) {
            int idx = tid + v * THREADS;
            if (TRANSB) {
                int r = idx / (BK / 4), c4 = idx % (BK / 4);
                pb[v] = *reinterpret_cast<const float4*>(&B[(size_t)(bn0 + r) * K + k0 + c4 * 4]);
            } else {
                int r = idx / (BN / 4), c4 = idx % (BN / 4);
                pb[v] = *reinterpret_cast<const float4*>(&B[(size_t)(k0 + r) * N + bn0 + c4 * 4]);
            }
        }
    };
    auto storeB = [&]() {
#pragma unroll
        for (int v = 0; v < BV; v++) {
            int idx = tid + v * THREADS;
            if (TRANSB) {
                int r = idx / (BK / 4), c4 = idx % (BK / 4);
                Bs[c4 * 4 + 0][r] = pb[v].x;
                Bs[c4 * 4 + 1][r] = pb[v].y;
                Bs[c4 * 4 + 2][r] = pb[v].z;
                Bs[c4 * 4 + 3][r] = pb[v].w;
            } else {
                int r = idx / (BN / 4), c4 = idx % (BN / 4);
                *reinterpret_cast<float4*>(&Bs[r][c4 * 4]) = pb[v];
            }
        }
    };

    loadA(kbeg); loadB(kbeg);
    storeA();    storeB();
    __syncthreads();

    for (int k0 = kbeg; k0 < kend; k0 += BK) {
        const bool more = (k0 + BK) < kend;
        if (more) { loadA(k0 + BK); loadB(k0 + BK); }

#pragma unroll
        for (int kk = 0; kk < BK; ++kk) {
            float a[TM], b[TN];
#pragma unroll
            for (int m = 0; m < TM; m += 4)
                *reinterpret_cast<float4*>(&a[m]) =
                    *reinterpret_cast<const float4*>(&As[kk][ty * TM + m]);
#pragma unroll
            for (int n = 0; n < TN; n += 4)
                *reinterpret_cast<float4*>(&b[n]) =
                    *reinterpret_cast<const float4*>(&Bs[kk][tx * TN + n]);
#pragma unroll
            for (int m = 0; m < TM; m++)
#pragma unroll
                for (int n = 0; n < TN; n++)
                    acc[m][n] = fmaf(a[m], b[n], acc[m][n]);
        }
        __syncthreads();
        if (more) { storeA(); storeB(); }
        __syncthreads();
    }

    // --- epilogue (vectorized stores) ---
#pragma unroll
    for (int m = 0; m < TM; m++) {
        int row = bm0 + ty * TM + m;
#pragma unroll
        for (int n0 = 0; n0 < TN; n0 += 4) {
            int col = bn0 + tx * TN + n0;
            float4 v;
            v.x = acc[m][n0 + 0];
            v.y = acc[m][n0 + 1];
            v.z = acc[m][n0 + 2];
            v.w = acc[m][n0 + 3];
            if (BIAS) {
                v.x += bias[col + 0];
                v.y += bias[col + 1];
                v.z += bias[col + 2];
                v.w += bias[col + 3];
            }
            if (RELU) {
                v.x = fmaxf(v.x, 0.0f);
                v.y = fmaxf(v.y, 0.0f);
                v.z = fmaxf(v.z, 0.0f);
                v.w = fmaxf(v.w, 0.0f);
            }
            *reinterpret_cast<float4*>(&C[(size_t)row * N + col]) = v;
        }
    }
}

// ---------------------------------------------------------------------------
// Reduce KSPLITS partial C buffers (deterministic fixed order), float4.
// ---------------------------------------------------------------------------
__global__ void __launch_bounds__(256)
reduce4_kernel(const float* __restrict__ P, float* __restrict__ C, int n) {
    int i = (blockIdx.x * blockDim.x + threadIdx.x) * 4;
    if (i < n) {
        float4 a = *reinterpret_cast<const float4*>(&P[i]);
        float4 b = *reinterpret_cast<const float4*>(&P[n + i]);
        float4 c = *reinterpret_cast<const float4*>(&P[2 * (size_t)n + i]);
        float4 d = *reinterpret_cast<const float4*>(&P[3 * (size_t)n + i]);
        float4 o;
        o.x = (a.x + b.x) + (c.x + d.x);
        o.y = (a.y + b.y) + (c.y + d.y);
        o.z = (a.z + b.z) + (c.z + d.z);
        o.w = (a.w + b.w) + (c.w + d.w);
        *reinterpret_cast<float4*>(&C[i]) = o;
    }
}

// ---------------------------------------------------------------------------
// Final layer: y[b][d] = sum_h H[b][h] * W2[d][h] + b2[d]   (DY=10, H=2048)
// One block per batch row, float4 loads, warp-shuffle + smem reduction.
// ---------------------------------------------------------------------------
__global__ void __launch_bounds__(256)
final_layer_kernel(const float* __restrict__ Hbuf, const float* __restrict__ W2,
                   const float* __restrict__ b2, float* __restrict__ y) {
    int b = blockIdx.x;
    const float4* hr = reinterpret_cast<const float4*>(Hbuf + (size_t)b * HH);

    float acc[DY];
#pragma unroll
    for (int d = 0; d < DY; d++) acc[d] = 0.0f;

    for (int i = threadIdx.x; i < HH / 4; i += 256) {
        float4 h4 = hr[i];
#pragma unroll
        for (int d = 0; d < DY; d++) {
            float4 w = *reinterpret_cast<const float4*>(&W2[(size_t)d * HH + i * 4]);
            acc[d] = fmaf(h4.x, w.x, acc[d]);
            acc[d] = fmaf(h4.y, w.y, acc[d]);
            acc[d] = fmaf(h4.z, w.z, acc[d]);
            acc[d] = fmaf(h4.w, w.w, acc[d]);
        }
    }

    // warp reduction
#pragma unroll
    for (int off = 16; off > 0; off >>= 1)
#pragma unroll
        for (int d = 0; d < DY; d++)
            acc[d] += __shfl_xor_sync(0xFFFFFFFFu, acc[d], off);

    __shared__ float red[8][DY];
    int w = threadIdx.x >> 5, l = threadIdx.x & 31;
    if (l == 0)
#pragma unroll
        for (int d = 0; d < DY; d++) red[w][d] = acc[d];
    __syncthreads();

    if (threadIdx.x < DY) {
        float s = b2[threadIdx.x];
#pragma unroll
        for (int ww = 0; ww < 8; ww++) s += red[ww][threadIdx.x];
        y[(size_t)b * DY + threadIdx.x] = s;
    }
}

// ---------------------------------------------------------------------------
// Launch
// ---------------------------------------------------------------------------
extern "C" void kernel_launch(void* const* d_in, const int* in_sizes, int n_in,
                              void* d_out, int out_size) {
    const float* x  = (const float*)d_in[0];
    const float* A  = (const float*)d_in[1];
    const float* W1 = (const float*)d_in[2];
    const float* b1 = (const float*)d_in[3];
    const float* W2 = (const float*)d_in[4];
    const float* b2 = (const float*)d_in[5];
    float* y = (float*)d_out;

    float *M0, *M1, *Part, *W1eff, *Hbuf;
    cudaGetSymbolAddress((void**)&M0, g_M0);
    cudaGetSymbolAddress((void**)&M1, g_M1);
    cudaGetSymbolAddress((void**)&Part, g_Part);
    cudaGetSymbolAddress((void**)&W1eff, g_W1eff);
    cudaGetSymbolAddress((void**)&Hbuf, g_H);

    // 1) M = I + dt * A^T
    {
        dim3 blk(16, 16), grd(DZ / 16, DZ / 16);
        build_M_kernel<<<grd, blk>>>(A, M0, 1.0f / (float)NSTEPS);
    }

    // 2) M^64 via 6 squarings, split-K (4 slices) + deterministic reduce
    float* src = M0;
    float* dst = M1;
    const int Ks = DZ / KSPLITS;  // 128
    for (int s = 0; s < 6; ++s) {
        dim3 grd(DZ / 64, DZ / 64, KSPLITS);  // (8, 8, 4) = 256 CTAs
        sgemm2<64, 64, 16, 4, 4, /*TRANSB=*/false, false, false, /*SPLITK=*/true>
            <<<grd, 256>>>(src, src, nullptr, Part, DZ, DZ, DZ, Ks);
        reduce4_kernel<<<(DZ * DZ / 4 + 255) / 256, 256>>>(Part, dst, DZ * DZ);
        float* t = src; src = dst; dst = t;
    }
    // result (M^64) now in src

    // 3) W1eff = W1 @ (M^64)^T
    {
        dim3 grd(DZ / 64, HH / 64);  // (8, 32) = 256 CTAs
        sgemm2<64, 64, 16, 4, 4, /*TRANSB=*/true, false, false, false>
            <<<grd, 256>>>(W1, src, nullptr, W1eff, HH, DZ, DZ, 0);
    }

    // 4) H = relu(x @ W1eff^T + b1)  — 4096 x 2048 x 512
    {
        dim3 grd(HH / 128, BB / 128);  // (16, 32) = 512 CTAs
        sgemm2<128, 128, 16, 8, 8, /*TRANSB=*/true, /*RELU=*/true, /*BIAS=*/true, false>
            <<<grd, 256>>>(x, W1eff, b1, Hbuf, BB, HH, DZ, 0);
    }

    // 5) y = H @ W2^T + b2
    final_layer_kernel<<<BB, 256>>>(Hbuf, W2, b2, y);
}

// round 4
// speedup vs baseline: 2.0644x; 1.5201x over previous
#include <cuda_runtime.h>
#include <cuda_bf16.h>
#include <cstdint>

// Problem constants (fixed by the dataset)
#define BB   4096
#define DZ   512
#define HH   2048
#define DY   10
#define NSTEPS 64
#define KSPLITS 4

// Scratch (allocation-free rule: __device__ globals)
__device__ float g_M0[DZ * DZ];
__device__ float g_M1[DZ * DZ];
__device__ float g_Part[KSPLITS * DZ * DZ];
__device__ float g_W1eff[HH * DZ];
__device__ float g_H[(size_t)BB * HH];
__device__ __nv_bfloat16 g_xh[(size_t)BB * DZ];
__device__ __nv_bfloat16 g_xl[(size_t)BB * DZ];
__device__ __nv_bfloat16 g_wh[(size_t)HH * DZ];
__device__ __nv_bfloat16 g_wl[(size_t)HH * DZ];

// ===========================================================================
// helpers: smem addr, cp.async, ldmatrix, mma (all base-arch instructions)
// ===========================================================================
__device__ __forceinline__ uint32_t smem_u32(const void* p) {
    uint32_t a;
    asm("{ .reg .u64 t; cvta.to.shared.u64 t, %1; cvt.u32.u64 %0, t; }"
        : "=r"(a) : "l"(p));
    return a;
}
__device__ __forceinline__ void cpasync16(uint32_t dst, const void* src) {
    asm volatile("cp.async.cg.shared.global [%0], [%1], 16;" :: "r"(dst), "l"(src));
}
#define CP_COMMIT() asm volatile("cp.async.commit_group;" ::: "memory")
#define CP_WAIT(n)  asm volatile("cp.async.wait_group %0;" :: "n"(n) : "memory")

__device__ __forceinline__ void ldmx4(uint32_t* r, uint32_t addr) {
    asm volatile("ldmatrix.sync.aligned.m8n8.x4.shared.b16 {%0,%1,%2,%3}, [%4];"
                 : "=r"(r[0]), "=r"(r[1]), "=r"(r[2]), "=r"(r[3]) : "r"(addr));
}
__device__ __forceinline__ void mma16816(float* d, const uint32_t* a, const uint32_t* b) {
    asm volatile(
        "mma.sync.aligned.m16n8k16.row.col.f32.bf16.bf16.f32 "
        "{%0,%1,%2,%3}, {%4,%5,%6,%7}, {%8,%9}, {%0,%1,%2,%3};"
        : "+f"(d[0]), "+f"(d[1]), "+f"(d[2]), "+f"(d[3])
        : "r"(a[0]), "r"(a[1]), "r"(a[2]), "r"(a[3]), "r"(b[0]), "r"(b[1]));
}

// ===========================================================================
// build M = I + dt * A^T
// ===========================================================================
__global__ void build_M_kernel(const float* __restrict__ A, float* __restrict__ M, float dt) {
    int j = blockIdx.x * blockDim.x + threadIdx.x;
    int i = blockIdx.y * blockDim.y + threadIdx.y;
    if (i < DZ && j < DZ) {
        float v = dt * A[(size_t)j * DZ + i];
        if (i == j) v += 1.0f;
        M[(size_t)i * DZ + j] = v;
    }
}

// ===========================================================================
// bf16 hi/lo split: hi = bf16(v), lo = bf16(v - hi)
// ===========================================================================
__global__ void __launch_bounds__(256)
split_kernel(const float* __restrict__ src, __nv_bfloat16* __restrict__ hi,
             __nv_bfloat16* __restrict__ lo, int n) {
    int i = (blockIdx.x * blockDim.x + threadIdx.x) * 4;
    if (i < n) {
        float4 v = *reinterpret_cast<const float4*>(&src[i]);
        __nv_bfloat16 h0 = __float2bfloat16(v.x);
        __nv_bfloat16 h1 = __float2bfloat16(v.y);
        __nv_bfloat16 h2 = __float2bfloat16(v.z);
        __nv_bfloat16 h3 = __float2bfloat16(v.w);
        __nv_bfloat16 l0 = __float2bfloat16(v.x - __bfloat162float(h0));
        __nv_bfloat16 l1 = __float2bfloat16(v.y - __bfloat162float(h1));
        __nv_bfloat16 l2 = __float2bfloat16(v.z - __bfloat162float(h2));
        __nv_bfloat16 l3 = __float2bfloat16(v.w - __bfloat162float(h3));
        __nv_bfloat162 hp0(h0, h1), hp1(h2, h3), lp0(l0, l1), lp1(l2, l3);
        *reinterpret_cast<__nv_bfloat162*>(&hi[i])     = hp0;
        *reinterpret_cast<__nv_bfloat162*>(&hi[i + 2]) = hp1;
        *reinterpret_cast<__nv_bfloat162*>(&lo[i])     = lp0;
        *reinterpret_cast<__nv_bfloat162*>(&lo[i + 2]) = lp1;
    }
}

// ===========================================================================
// Main GEMM via mma.sync bf16x3:  H = relu(x @ W1eff^T + b1)
// Block tile 128x128, BK=32, 8 warps (4m x 2n), warp tile 32x64.
// Smem: [2 buffers][Ah, Al, Bh, Bl], each tile 128 rows x 32 bf16, pitch 40.
// ===========================================================================
#define BMM 128
#define BNN 128
#define BKK 32
#define PITCH 40
#define TSZ (BMM * PITCH)                       // bf16 elems per tile = 5120
#define MMA_SMEM (2 * 4 * TSZ * 2)              // 81920 bytes

__global__ void __launch_bounds__(256, 1)
mlp1_mma_kernel(const __nv_bfloat16* __restrict__ xh, const __nv_bfloat16* __restrict__ xl,
                const __nv_bfloat16* __restrict__ wh, const __nv_bfloat16* __restrict__ wl,
                const float* __restrict__ b1, float* __restrict__ Hout) {
    extern __shared__ __nv_bfloat16 sm[];
    const int tid  = threadIdx.x;
    const int wid  = tid >> 5;
    const int lane = tid & 31;
    const int bn0  = blockIdx.x * BNN;
    const int bm0  = blockIdx.y * BMM;
    const uint32_t sbase = smem_u32(sm);

    const int warp_m = wid >> 1;         // 0..3
    const int warp_n = wid & 1;          // 0..1
    const int m_base = warp_m * 32;
    const int n_base = warp_n * 64;

    // stage one BK-chunk (all 4 tiles) into buffer `buf` with cp.async
    auto stage = [&](int buf, int k0) {
        const __nv_bfloat16* srcs[4] = {xh + (size_t)bm0 * DZ, xl + (size_t)bm0 * DZ,
                                        wh + (size_t)bn0 * DZ, wl + (size_t)bn0 * DZ};
        uint32_t bb = sbase + (uint32_t)buf * 4 * TSZ * 2;
#pragma unroll
        for (int tile = 0; tile < 4; ++tile) {
            const __nv_bfloat16* s = srcs[tile];
            uint32_t tb = bb + tile * TSZ * 2;
#pragma unroll
            for (int t = 0; t < 2; ++t) {
                int idx = tid + t * 256;          // 512 16B-chunks per tile
                int row = idx >> 2, c16 = idx & 3;
                cpasync16(tb + (uint32_t)(row * PITCH + c16 * 8) * 2,
                          s + (size_t)row * DZ + k0 + c16 * 8);
            }
        }
        CP_COMMIT();
    };

    float c[2][8][4];
#pragma unroll
    for (int mt = 0; mt < 2; mt++)
#pragma unroll
        for (int j = 0; j < 8; j++)
#pragma unroll
            for (int q = 0; q < 4; q++) c[mt][j][q] = 0.0f;

    stage(0, 0);

    for (int it = 0; it < DZ / BKK; ++it) {      // 16 iterations
        if (it + 1 < DZ / BKK) { stage((it + 1) & 1, (it + 1) * BKK); CP_WAIT(1); }
        else                   { CP_WAIT(0); }
        __syncthreads();

        uint32_t bb = sbase + (uint32_t)(it & 1) * 4 * TSZ * 2;
        uint32_t Ah_b = bb, Al_b = bb + TSZ * 2, Bh_b = bb + 2 * TSZ * 2, Bl_b = bb + 3 * TSZ * 2;

#pragma unroll
        for (int ks = 0; ks < 2; ++ks) {
            int kc = ks * 16;
            // ---- A fragments (2 m-tiles x hi/lo) ----
            uint32_t ah[2][4], al[2][4];
#pragma unroll
            for (int mt = 0; mt < 2; ++mt) {
                uint32_t roff = (uint32_t)((m_base + mt * 16 + (lane & 15)) * PITCH
                                           + kc + ((lane >> 4) << 3)) * 2;
                ldmx4(ah[mt], Ah_b + roff);
                ldmx4(al[mt], Al_b + roff);
            }
            // ---- B fragments, pair of n-tiles at a time; mma immediately ----
#pragma unroll
            for (int jp = 0; jp < 4; ++jp) {
                int n0 = n_base + jp * 16;
                uint32_t roff = (uint32_t)((n0 + (lane & 7) + ((lane >> 4) << 3)) * PITCH
                                           + kc + (((lane >> 3) & 1) << 3)) * 2;
                uint32_t bh[4], bl[4];
                ldmx4(bh, Bh_b + roff);
                ldmx4(bl, Bl_b + roff);
#pragma unroll
                for (int mt = 0; mt < 2; ++mt) {
                    mma16816(c[mt][2 * jp + 0], ah[mt], bh + 0);
                    mma16816(c[mt][2 * jp + 0], ah[mt], bl + 0);
                    mma16816(c[mt][2 * jp + 0], al[mt], bh + 0);
                    mma16816(c[mt][2 * jp + 1], ah[mt], bh + 2);
                    mma16816(c[mt][2 * jp + 1], ah[mt], bl + 2);
                    mma16816(c[mt][2 * jp + 1], al[mt], bh + 2);
                }
            }
        }
        __syncthreads();
    }

    // ---- epilogue: bias + relu, write fp32 ----
    const int g  = lane >> 2;
    const int t4 = lane & 3;
#pragma unroll
    for (int mt = 0; mt < 2; ++mt) {
        int row0 = bm0 + m_base + mt * 16 + g;
#pragma unroll
        for (int j = 0; j < 8; ++j) {
            int col = bn0 + n_base + j * 8 + t4 * 2;
            float bx = b1[col], by = b1[col + 1];
            float2 v0, v1;
            v0.x = fmaxf(c[mt][j][0] + bx, 0.0f);
            v0.y = fmaxf(c[mt][j][1] + by, 0.0f);
            v1.x = fmaxf(c[mt][j][2] + bx, 0.0f);
            v1.y = fmaxf(c[mt][j][3] + by, 0.0f);
            *reinterpret_cast<float2*>(&Hout[(size_t)row0 * HH + col])       = v0;
            *reinterpret_cast<float2*>(&Hout[(size_t)(row0 + 8) * HH + col]) = v1;
        }
    }
}

// ===========================================================================
// SIMT SGEMM (register prefetch) — squarings + W1eff
// ===========================================================================
template <int BM, int BN, int BK, int TM, int TN, bool TRANSB, bool RELU, bool BIAS, bool SPLITK>
__global__ void __launch_bounds__((BM / TM) * (BN / TN))
sgemm2(const float* __restrict__ A, const float* __restrict__ B,
       const float* __restrict__ bias, float* __restrict__ C,
       int M, int N, int K, int Ksplit) {
    constexpr int THREADS = (BM / TM) * (BN / TN);
    constexpr int AV = BM * BK / (4 * THREADS);
    constexpr int BV = BN * BK / (4 * THREADS);
    const int tid = threadIdx.x;
    const int tx  = tid % (BN / TN);
    const int ty  = tid / (BN / TN);
    const int bm0 = blockIdx.y * BM;
    const int bn0 = blockIdx.x * BN;

    int kbeg = 0, kend = K;
    if (SPLITK) {
        kbeg = blockIdx.z * Ksplit;
        kend = kbeg + Ksplit;
        C += (size_t)blockIdx.z * M * N;
    }

    __shared__ float As[BK][BM];
    __shared__ float Bs[BK][BN];

    float acc[TM][TN];
#pragma unroll
    for (int m = 0; m < TM; m++)
#pragma unroll
        for (int n = 0; n < TN; n++) acc[m][n] = 0.0f;

    float4 pa[AV], pb[BV];

    auto loadA = [&](int k0) {
#pragma unroll
        for (int v = 0; v < AV; v++) {
            int idx = tid + v * THREADS;
            int r = idx / (BK / 4), c4 = idx % (BK / 4);
            pa[v] = *reinterpret_cast<const float4*>(&A[(size_t)(bm0 + r) * K + k0 + c4 * 4]);
        }
    };
    auto storeA = [&]() {
#pragma unroll
        for (int v = 0; v < AV; v++) {
            int idx = tid + v * THREADS;
            int r = idx / (BK / 4), c4 = idx % (BK / 4);
            As[c4 * 4 + 0][r] = pa[v].x;
            As[c4 * 4 + 1][r] = pa[v].y;
            As[c4 * 4 + 2][r] = pa[v].z;
            As[c4 * 4 + 3][r] = pa[v].w;
        }
    };
    auto loadB = [&](int k0) {
#pragma unroll
        for (int v = 0; v < BV; v++) {
            int idx = tid + v * THREADS;
            if (TRANSB) {
                int r = idx / (BK / 4), c4 = idx % (BK / 4);
                pb[v] = *reinterpret_cast<const float4*>(&B[(size_t)(bn0 + r) * K + k0 + c4 * 4]);
            } else {
                int r = idx / (BN / 4), c4 = idx % (BN / 4);
                pb[v] = *reinterpret_cast<const float4*>(&B[(size_t)(k0 + r) * N + bn0 + c4 * 4]);
            }
        }
    };
    auto storeB = [&]() {
#pragma unroll
        for (int v = 0; v < BV; v++) {
            int idx = tid + v * THREADS;
            if (TRANSB) {
                int r = idx / (BK / 4), c4 = idx % (BK / 4);
                Bs[c4 * 4 + 0][r] = pb[v].x;
                Bs[c4 * 4 + 1][r] = pb[v].y;
                Bs[c4 * 4 + 2][r] = pb[v].z;
                Bs[c4 * 4 + 3][r] = pb[v].w;
            } else {
                int r = idx / (BN / 4), c4 = idx % (BN / 4);
                *reinterpret_cast<float4*>(&Bs[r][c4 * 4]) = pb[v];
            }
        }
    };

    loadA(kbeg); loadB(kbeg);
    storeA();    storeB();
    __syncthreads();

    for (int k0 = kbeg; k0 < kend; k0 += BK) {
        const bool more = (k0 + BK) < kend;
        if (more) { loadA(k0 + BK); loadB(k0 + BK); }

#pragma unroll
        for (int kk = 0; kk < BK; ++kk) {
            float a[TM], b[TN];
#pragma unroll
            for (int m = 0; m < TM; m += 4)
                *reinterpret_cast<float4*>(&a[m]) =
                    *reinterpret_cast<const float4*>(&As[kk][ty * TM + m]);
#pragma unroll
            for (int n = 0; n < TN; n += 4)
                *reinterpret_cast<float4*>(&b[n]) =
                    *reinterpret_cast<const float4*>(&Bs[kk][tx * TN + n]);
#pragma unroll
            for (int m = 0; m < TM; m++)
#pragma unroll
                for (int n = 0; n < TN; n++)
                    acc[m][n] = fmaf(a[m], b[n], acc[m][n]);
        }
        __syncthreads();
        if (more) { storeA(); storeB(); }
        __syncthreads();
    }

#pragma unroll
    for (int m = 0; m < TM; m++) {
        int row = bm0 + ty * TM + m;
#pragma unroll
        for (int n0 = 0; n0 < TN; n0 += 4) {
            int col = bn0 + tx * TN + n0;
            float4 v;
            v.x = acc[m][n0 + 0];
            v.y = acc[m][n0 + 1];
            v.z = acc[m][n0 + 2];
            v.w = acc[m][n0 + 3];
            if (BIAS) {
                v.x += bias[col + 0];
                v.y += bias[col + 1];
                v.z += bias[col + 2];
                v.w += bias[col + 3];
            }
            if (RELU) {
                v.x = fmaxf(v.x, 0.0f);
                v.y = fmaxf(v.y, 0.0f);
                v.z = fmaxf(v.z, 0.0f);
                v.w = fmaxf(v.w, 0.0f);
            }
            *reinterpret_cast<float4*>(&C[(size_t)row * N + col]) = v;
        }
    }
}

// ===========================================================================
// Reduce KSPLITS partial buffers (deterministic order)
// ===========================================================================
__global__ void __launch_bounds__(256)
reduce4_kernel(const float* __restrict__ P, float* __restrict__ C, int n) {
    int i = (blockIdx.x * blockDim.x + threadIdx.x) * 4;
    if (i < n) {
        float4 a = *reinterpret_cast<const float4*>(&P[i]);
        float4 b = *reinterpret_cast<const float4*>(&P[n + i]);
        float4 c = *reinterpret_cast<const float4*>(&P[2 * (size_t)n + i]);
        float4 d = *reinterpret_cast<const float4*>(&P[3 * (size_t)n + i]);
        float4 o;
        o.x = (a.x + b.x) + (c.x + d.x);
        o.y = (a.y + b.y) + (c.y + d.y);
        o.z = (a.z + b.z) + (c.z + d.z);
        o.w = (a.w + b.w) + (c.w + d.w);
        *reinterpret_cast<float4*>(&C[i]) = o;
    }
}

// ===========================================================================
// Final layer: y = H @ W2^T + b2
// ===========================================================================
__global__ void __launch_bounds__(256)
final_layer_kernel(const float* __restrict__ Hbuf, const float* __restrict__ W2,
                   const float* __restrict__ b2, float* __restrict__ y) {
    int b = blockIdx.x;
    const float4* hr = reinterpret_cast<const float4*>(Hbuf + (size_t)b * HH);

    float acc[DY];
#pragma unroll
    for (int d = 0; d < DY; d++) acc[d] = 0.0f;

    for (int i = threadIdx.x; i < HH / 4; i += 256) {
        float4 h4 = hr[i];
#pragma unroll
        for (int d = 0; d < DY; d++) {
            float4 w = *reinterpret_cast<const float4*>(&W2[(size_t)d * HH + i * 4]);
            acc[d] = fmaf(h4.x, w.x, acc[d]);
            acc[d] = fmaf(h4.y, w.y, acc[d]);
            acc[d] = fmaf(h4.z, w.z, acc[d]);
            acc[d] = fmaf(h4.w, w.w, acc[d]);
        }
    }

#pragma unroll
    for (int off = 16; off > 0; off >>= 1)
#pragma unroll
        for (int d = 0; d < DY; d++)
            acc[d] += __shfl_xor_sync(0xFFFFFFFFu, acc[d], off);

    __shared__ float red[8][DY];
    int w = threadIdx.x >> 5, l = threadIdx.x & 31;
    if (l == 0)
#pragma unroll
        for (int d = 0; d < DY; d++) red[w][d] = acc[d];
    __syncthreads();

    if (threadIdx.x < DY) {
        float s = b2[threadIdx.x];
#pragma unroll
        for (int ww = 0; ww < 8; ww++) s += red[ww][threadIdx.x];
        y[(size_t)b * DY + threadIdx.x] = s;
    }
}

// ===========================================================================
// Launch
// ===========================================================================
extern "C" void kernel_launch(void* const* d_in, const int* in_sizes, int n_in,
                              void* d_out, int out_size) {
    const float* x  = (const float*)d_in[0];
    const float* A  = (const float*)d_in[1];
    const float* W1 = (const float*)d_in[2];
    const float* b1 = (const float*)d_in[3];
    const float* W2 = (const float*)d_in[4];
    const float* b2 = (const float*)d_in[5];
    float* y = (float*)d_out;

    float *M0, *M1, *Part, *W1eff, *Hbuf;
    __nv_bfloat16 *xh, *xl, *wh, *wl;
    cudaGetSymbolAddress((void**)&M0, g_M0);
    cudaGetSymbolAddress((void**)&M1, g_M1);
    cudaGetSymbolAddress((void**)&Part, g_Part);
    cudaGetSymbolAddress((void**)&W1eff, g_W1eff);
    cudaGetSymbolAddress((void**)&Hbuf, g_H);
    cudaGetSymbolAddress((void**)&xh, g_xh);
    cudaGetSymbolAddress((void**)&xl, g_xl);
    cudaGetSymbolAddress((void**)&wh, g_wh);
    cudaGetSymbolAddress((void**)&wl, g_wl);

    cudaFuncSetAttribute(mlp1_mma_kernel,
                         cudaFuncAttributeMaxDynamicSharedMemorySize, MMA_SMEM);

    // 1) M = I + dt * A^T
    {
        dim3 blk(16, 16), grd(DZ / 16, DZ / 16);
        build_M_kernel<<<grd, blk>>>(A, M0, 1.0f / (float)NSTEPS);
    }

    // split x early (independent of the ODE chain)
    split_kernel<<<(BB * DZ / 4 + 255) / 256, 256>>>(x, xh, xl, BB * DZ);

    // 2) M^64 via 6 squarings, split-K + deterministic reduce
    float* src = M0;
    float* dst = M1;
    const int Ks = DZ / KSPLITS;
    for (int s = 0; s < 6; ++s) {
        dim3 grd(DZ / 64, DZ / 64, KSPLITS);
        sgemm2<64, 64, 16, 4, 4, false, false, false, true>
            <<<grd, 256>>>(src, src, nullptr, Part, DZ, DZ, DZ, Ks);
        reduce4_kernel<<<(DZ * DZ / 4 + 255) / 256, 256>>>(Part, dst, DZ * DZ);
        float* t = src; src = dst; dst = t;
    }

    // 3) W1eff = W1 @ (M^64)^T
    {
        dim3 grd(DZ / 64, HH / 64);
        sgemm2<64, 64, 16, 4, 4, true, false, false, false>
            <<<grd, 256>>>(W1, src, nullptr, W1eff, HH, DZ, DZ, 0);
    }

    // split W1eff
    split_kernel<<<(HH * DZ / 4 + 255) / 256, 256>>>(W1eff, wh, wl, HH * DZ);

    // 4) H = relu(x @ W1eff^T + b1) — mma.sync bf16x3
    {
        dim3 grd(HH / BNN, BB / BMM);  // (16, 32)
        mlp1_mma_kernel<<<grd, 256, MMA_SMEM>>>(xh, xl, wh, wl, b1, Hbuf);
    }

    // 5) y = H @ W2^T + b2
    final_layer_kernel<<<BB, 256>>>(Hbuf, W2, b2, y);
}

// round 5
// speedup vs baseline: 2.2367x; 1.0835x over previous
#include <cuda_runtime.h>
#include <cuda_bf16.h>
#include <cstdint>

// Problem constants (fixed by the dataset)
#define BB   4096
#define DZ   512
#define HH   2048
#define DY   10
#define NSTEPS 64

// Scratch (allocation-free rule: __device__ globals)
// S state: [pingpong][ Sh | Sl | STh | STl ], each DZ*DZ bf16
__device__ __nv_bfloat16 g_S[2][4][DZ * DZ];
__device__ float g_H[(size_t)BB * HH];
__device__ __nv_bfloat16 g_xh[(size_t)BB * DZ];
__device__ __nv_bfloat16 g_xl[(size_t)BB * DZ];
__device__ __nv_bfloat16 g_w1h[(size_t)HH * DZ];
__device__ __nv_bfloat16 g_w1l[(size_t)HH * DZ];
__device__ __nv_bfloat16 g_wh[(size_t)HH * DZ];
__device__ __nv_bfloat16 g_wl[(size_t)HH * DZ];

// ===========================================================================
// helpers (base-arch instructions only: cp.async, ldmatrix, mma.sync)
// ===========================================================================
__device__ __forceinline__ uint32_t smem_u32(const void* p) {
    uint32_t a;
    asm("{ .reg .u64 t; cvta.to.shared.u64 t, %1; cvt.u32.u64 %0, t; }"
        : "=r"(a) : "l"(p));
    return a;
}
__device__ __forceinline__ void cpasync16(uint32_t dst, const void* src) {
    asm volatile("cp.async.cg.shared.global [%0], [%1], 16;" :: "r"(dst), "l"(src));
}
#define CP_COMMIT() asm volatile("cp.async.commit_group;" ::: "memory")
#define CP_WAIT(n)  asm volatile("cp.async.wait_group %0;" :: "n"(n) : "memory")

__device__ __forceinline__ void ldmx4(uint32_t* r, uint32_t addr) {
    asm volatile("ldmatrix.sync.aligned.m8n8.x4.shared.b16 {%0,%1,%2,%3}, [%4];"
                 : "=r"(r[0]), "=r"(r[1]), "=r"(r[2]), "=r"(r[3]) : "r"(addr));
}
__device__ __forceinline__ void mma16816(float* d, const uint32_t* a, const uint32_t* b) {
    asm volatile(
        "mma.sync.aligned.m16n8k16.row.col.f32.bf16.bf16.f32 "
        "{%0,%1,%2,%3}, {%4,%5,%6,%7}, {%8,%9}, {%0,%1,%2,%3};"
        : "+f"(d[0]), "+f"(d[1]), "+f"(d[2]), "+f"(d[3])
        : "r"(a[0]), "r"(a[1]), "r"(a[2]), "r"(a[3]), "r"(b[0]), "r"(b[1]));
}
__device__ __forceinline__ void split2(float v, __nv_bfloat16& h, __nv_bfloat16& l) {
    h = __float2bfloat16(v);
    l = __float2bfloat16(v - __bfloat162float(h));
}

// ===========================================================================
// build S = I + dt*A^T as bf16 hi/lo, plus transposed copies (smem transpose)
// S[i][j] = (i==j) + dt*A[j][i];  ST = S^T (i.e. I + dt*A)
// ===========================================================================
__global__ void __launch_bounds__(256)
build_MT_kernel(const float* __restrict__ A,
                __nv_bfloat16* __restrict__ Sh, __nv_bfloat16* __restrict__ Sl,
                __nv_bfloat16* __restrict__ STh, __nv_bfloat16* __restrict__ STl,
                float dt) {
    __shared__ float tile[16][17];
    int tx = threadIdx.x, ty = threadIdx.y;
    int i0 = blockIdx.x * 16, j0 = blockIdx.y * 16;
    int i = i0 + tx, j = j0 + ty;
    // coalesced read of A row j
    float v = dt * A[(size_t)j * DZ + i];
    if (i == j) v += 1.0f;
    // ST[j][i] = v : coalesced in tx
    __nv_bfloat16 h, l;
    split2(v, h, l);
    STh[(size_t)j * DZ + i] = h;
    STl[(size_t)j * DZ + i] = l;
    tile[ty][tx] = v;   // tile[j_local][i_local]
    __syncthreads();
    // S[i][j] = v(i_local=ty, j_local=tx) = tile[tx][ty] : coalesced in tx
    float w = tile[tx][ty];
    split2(w, h, l);
    Sh[(size_t)(i0 + ty) * DZ + j0 + tx] = h;
    Sl[(size_t)(i0 + ty) * DZ + j0 + tx] = l;
}

// ===========================================================================
// bf16 hi/lo split of an fp32 array
// ===========================================================================
__global__ void __launch_bounds__(256)
split_kernel(const float* __restrict__ src, __nv_bfloat16* __restrict__ hi,
             __nv_bfloat16* __restrict__ lo, int n) {
    int i = (blockIdx.x * blockDim.x + threadIdx.x) * 4;
    if (i < n) {
        float4 v = *reinterpret_cast<const float4*>(&src[i]);
        __nv_bfloat16 h0, h1, h2, h3, l0, l1, l2, l3;
        split2(v.x, h0, l0); split2(v.y, h1, l1);
        split2(v.z, h2, l2); split2(v.w, h3, l3);
        *reinterpret_cast<__nv_bfloat162*>(&hi[i])     = __nv_bfloat162(h0, h1);
        *reinterpret_cast<__nv_bfloat162*>(&hi[i + 2]) = __nv_bfloat162(h2, h3);
        *reinterpret_cast<__nv_bfloat162*>(&lo[i])     = __nv_bfloat162(l0, l1);
        *reinterpret_cast<__nv_bfloat162*>(&lo[i + 2]) = __nv_bfloat162(l2, l3);
    }
}

// ===========================================================================
// Squaring kernel: C = S @ S  via NT mma (B operand = S^T rows), bf16x3.
// 64x64 tile, BK=32, 4 warps (2m x 2n), warp tile 32x32.
// Epilogue: re-split fp32 acc -> (S'h,S'l) and (optionally) (S'Th,S'Tl).
// ===========================================================================
#define SQ_PITCH 40
#define SQ_TSZ (64 * SQ_PITCH)                  // bf16 elems per tile
#define SQ_SMEM (2 * 4 * SQ_TSZ * 2)            // 40960 bytes

__global__ void __launch_bounds__(128, 1)
square_mma_kernel(const __nv_bfloat16* __restrict__ Ah, const __nv_bfloat16* __restrict__ Al,
                  const __nv_bfloat16* __restrict__ Bh, const __nv_bfloat16* __restrict__ Bl,
                  __nv_bfloat16* __restrict__ Ch, __nv_bfloat16* __restrict__ Cl,
                  __nv_bfloat16* __restrict__ CTh, __nv_bfloat16* __restrict__ CTl,
                  int write_t) {
    extern __shared__ __nv_bfloat16 sm[];
    const int tid  = threadIdx.x;
    const int wid  = tid >> 5;
    const int lane = tid & 31;
    const int bn0  = blockIdx.x * 64;
    const int bm0  = blockIdx.y * 64;
    const uint32_t sbase = smem_u32(sm);

    const int warp_m = wid >> 1;   // 0..1
    const int warp_n = wid & 1;    // 0..1
    const int m_base = warp_m * 32;
    const int n_base = warp_n * 32;

    auto stage = [&](int buf, int k0) {
        const __nv_bfloat16* srcs[4] = {Ah + (size_t)bm0 * DZ, Al + (size_t)bm0 * DZ,
                                        Bh + (size_t)bn0 * DZ, Bl + (size_t)bn0 * DZ};
        uint32_t bb = sbase + (uint32_t)buf * 4 * SQ_TSZ * 2;
#pragma unroll
        for (int tile = 0; tile < 4; ++tile) {
            uint32_t tb = bb + tile * SQ_TSZ * 2;
#pragma unroll
            for (int t = 0; t < 2; ++t) {
                int idx = tid + t * 128;      // 256 16B-chunks per tile
                int row = idx >> 2, c16 = idx & 3;
                cpasync16(tb + (uint32_t)(row * SQ_PITCH + c16 * 8) * 2,
                          srcs[tile] + (size_t)row * DZ + k0 + c16 * 8);
            }
        }
        CP_COMMIT();
    };

    float c[2][4][4];
#pragma unroll
    for (int mt = 0; mt < 2; mt++)
#pragma unroll
        for (int j = 0; j < 4; j++)
#pragma unroll
            for (int q = 0; q < 4; q++) c[mt][j][q] = 0.0f;

    stage(0, 0);

    for (int it = 0; it < DZ / 32; ++it) {        // 16 iterations
        if (it + 1 < DZ / 32) { stage((it + 1) & 1, (it + 1) * 32); CP_WAIT(1); }
        else                  { CP_WAIT(0); }
        __syncthreads();

        uint32_t bb = sbase + (uint32_t)(it & 1) * 4 * SQ_TSZ * 2;
        uint32_t Ah_b = bb, Al_b = bb + SQ_TSZ * 2, Bh_b = bb + 2 * SQ_TSZ * 2,
                 Bl_b = bb + 3 * SQ_TSZ * 2;

#pragma unroll
        for (int ks = 0; ks < 2; ++ks) {
            int kc = ks * 16;
            uint32_t ah[2][4], al[2][4];
#pragma unroll
            for (int mt = 0; mt < 2; ++mt) {
                uint32_t roff = (uint32_t)((m_base + mt * 16 + (lane & 15)) * SQ_PITCH
                                           + kc + ((lane >> 4) << 3)) * 2;
                ldmx4(ah[mt], Ah_b + roff);
                ldmx4(al[mt], Al_b + roff);
            }
#pragma unroll
            for (int jp = 0; jp < 2; ++jp) {
                int n0 = n_base + jp * 16;
                uint32_t roff = (uint32_t)((n0 + (lane & 7) + ((lane >> 4) << 3)) * SQ_PITCH
                                           + kc + (((lane >> 3) & 1) << 3)) * 2;
                uint32_t bh[4], bl[4];
                ldmx4(bh, Bh_b + roff);
                ldmx4(bl, Bl_b + roff);
#pragma unroll
                for (int mt = 0; mt < 2; ++mt) {
                    mma16816(c[mt][2 * jp + 0], ah[mt], bh + 0);
                    mma16816(c[mt][2 * jp + 0], ah[mt], bl + 0);
                    mma16816(c[mt][2 * jp + 0], al[mt], bh + 0);
                    mma16816(c[mt][2 * jp + 1], ah[mt], bh + 2);
                    mma16816(c[mt][2 * jp + 1], ah[mt], bl + 2);
                    mma16816(c[mt][2 * jp + 1], al[mt], bh + 2);
                }
            }
        }
        __syncthreads();
    }

    // epilogue: split fp32 acc into hi/lo; write C and (optionally) C^T
    const int g  = lane >> 2;
    const int t4 = lane & 3;
#pragma unroll
    for (int mt = 0; mt < 2; ++mt) {
        int r0 = bm0 + m_base + mt * 16 + g;
#pragma unroll
        for (int j = 0; j < 4; ++j) {
            int col = bn0 + n_base + j * 8 + t4 * 2;
            __nv_bfloat16 h00, l00, h01, l01, h10, l10, h11, l11;
            split2(c[mt][j][0], h00, l00);
            split2(c[mt][j][1], h01, l01);
            split2(c[mt][j][2], h10, l10);
            split2(c[mt][j][3], h11, l11);
            *reinterpret_cast<__nv_bfloat162*>(&Ch[(size_t)r0 * DZ + col])       = __nv_bfloat162(h00, h01);
            *reinterpret_cast<__nv_bfloat162*>(&Ch[(size_t)(r0 + 8) * DZ + col]) = __nv_bfloat162(h10, h11);
            *reinterpret_cast<__nv_bfloat162*>(&Cl[(size_t)r0 * DZ + col])       = __nv_bfloat162(l00, l01);
            *reinterpret_cast<__nv_bfloat162*>(&Cl[(size_t)(r0 + 8) * DZ + col]) = __nv_bfloat162(l10, l11);
            if (write_t) {
                CTh[(size_t)col * DZ + r0]             = h00;
                CTh[(size_t)(col + 1) * DZ + r0]       = h01;
                CTh[(size_t)col * DZ + r0 + 8]         = h10;
                CTh[(size_t)(col + 1) * DZ + r0 + 8]   = h11;
                CTl[(size_t)col * DZ + r0]             = l00;
                CTl[(size_t)(col + 1) * DZ + r0]       = l01;
                CTl[(size_t)col * DZ + r0 + 8]         = l10;
                CTl[(size_t)(col + 1) * DZ + r0 + 8]   = l11;
            }
        }
    }
}

// ===========================================================================
// Unified 128x128 NT mma kernel, bf16x3.  C = Amat @ Bmat^T, K = DZ = 512.
// EPI 0: out = relu(C + bias) as fp32, ld = N   (main MLP layer)
// EPI 1: out = hi/lo bf16 split of C, ld = N    (W1eff production)
// ===========================================================================
#define BMM 128
#define BNN 128
#define PITCH 40
#define TSZ (BMM * PITCH)
#define MMA_SMEM (2 * 4 * TSZ * 2)              // 81920 bytes

template <int EPI>
__global__ void __launch_bounds__(256, 1)
mma_nt_kernel(const __nv_bfloat16* __restrict__ Amh, const __nv_bfloat16* __restrict__ Aml,
              const __nv_bfloat16* __restrict__ Bmh, const __nv_bfloat16* __restrict__ Bml,
              const float* __restrict__ bias, float* __restrict__ outf,
              __nv_bfloat16* __restrict__ outh, __nv_bfloat16* __restrict__ outl,
              int N) {
    extern __shared__ __nv_bfloat16 sm[];
    const int tid  = threadIdx.x;
    const int wid  = tid >> 5;
    const int lane = tid & 31;
    const int bn0  = blockIdx.x * BNN;
    const int bm0  = blockIdx.y * BMM;
    const uint32_t sbase = smem_u32(sm);

    const int warp_m = wid >> 1;
    const int warp_n = wid & 1;
    const int m_base = warp_m * 32;
    const int n_base = warp_n * 64;

    auto stage = [&](int buf, int k0) {
        const __nv_bfloat16* srcs[4] = {Amh + (size_t)bm0 * DZ, Aml + (size_t)bm0 * DZ,
                                        Bmh + (size_t)bn0 * DZ, Bml + (size_t)bn0 * DZ};
        uint32_t bb = sbase + (uint32_t)buf * 4 * TSZ * 2;
#pragma unroll
        for (int tile = 0; tile < 4; ++tile) {
            uint32_t tb = bb + tile * TSZ * 2;
#pragma unroll
            for (int t = 0; t < 2; ++t) {
                int idx = tid + t * 256;
                int row = idx >> 2, c16 = idx & 3;
                cpasync16(tb + (uint32_t)(row * PITCH + c16 * 8) * 2,
                          srcs[tile] + (size_t)row * DZ + k0 + c16 * 8);
            }
        }
        CP_COMMIT();
    };

    float c[2][8][4];
#pragma unroll
    for (int mt = 0; mt < 2; mt++)
#pragma unroll
        for (int j = 0; j < 8; j++)
#pragma unroll
            for (int q = 0; q < 4; q++) c[mt][j][q] = 0.0f;

    stage(0, 0);

    for (int it = 0; it < DZ / 32; ++it) {
        if (it + 1 < DZ / 32) { stage((it + 1) & 1, (it + 1) * 32); CP_WAIT(1); }
        else                  { CP_WAIT(0); }
        __syncthreads();

        uint32_t bb = sbase + (uint32_t)(it & 1) * 4 * TSZ * 2;
        uint32_t Ah_b = bb, Al_b = bb + TSZ * 2, Bh_b = bb + 2 * TSZ * 2, Bl_b = bb + 3 * TSZ * 2;

#pragma unroll
        for (int ks = 0; ks < 2; ++ks) {
            int kc = ks * 16;
            uint32_t ah[2][4], al[2][4];
#pragma unroll
            for (int mt = 0; mt < 2; ++mt) {
                uint32_t roff = (uint32_t)((m_base + mt * 16 + (lane & 15)) * PITCH
                                           + kc + ((lane >> 4) << 3)) * 2;
                ldmx4(ah[mt], Ah_b + roff);
                ldmx4(al[mt], Al_b + roff);
            }
#pragma unroll
            for (int jp = 0; jp < 4; ++jp) {
                int n0 = n_base + jp * 16;
                uint32_t roff = (uint32_t)((n0 + (lane & 7) + ((lane >> 4) << 3)) * PITCH
                                           + kc + (((lane >> 3) & 1) << 3)) * 2;
                uint32_t bh[4], bl[4];
                ldmx4(bh, Bh_b + roff);
                ldmx4(bl, Bl_b + roff);
#pragma unroll
                for (int mt = 0; mt < 2; ++mt) {
                    mma16816(c[mt][2 * jp + 0], ah[mt], bh + 0);
                    mma16816(c[mt][2 * jp + 0], ah[mt], bl + 0);
                    mma16816(c[mt][2 * jp + 0], al[mt], bh + 0);
                    mma16816(c[mt][2 * jp + 1], ah[mt], bh + 2);
                    mma16816(c[mt][2 * jp + 1], ah[mt], bl + 2);
                    mma16816(c[mt][2 * jp + 1], al[mt], bh + 2);
                }
            }
        }
        __syncthreads();
    }

    const int g  = lane >> 2;
    const int t4 = lane & 3;
#pragma unroll
    for (int mt = 0; mt < 2; ++mt) {
        int row0 = bm0 + m_base + mt * 16 + g;
#pragma unroll
        for (int j = 0; j < 8; ++j) {
            int col = bn0 + n_base + j * 8 + t4 * 2;
            if (EPI == 0) {
                float bx = bias[col], by = bias[col + 1];
                float2 v0, v1;
                v0.x = fmaxf(c[mt][j][0] + bx, 0.0f);
                v0.y = fmaxf(c[mt][j][1] + by, 0.0f);
                v1.x = fmaxf(c[mt][j][2] + bx, 0.0f);
                v1.y = fmaxf(c[mt][j][3] + by, 0.0f);
                *reinterpret_cast<float2*>(&outf[(size_t)row0 * N + col])       = v0;
                *reinterpret_cast<float2*>(&outf[(size_t)(row0 + 8) * N + col]) = v1;
            } else {
                __nv_bfloat16 h00, l00, h01, l01, h10, l10, h11, l11;
                split2(c[mt][j][0], h00, l00);
                split2(c[mt][j][1], h01, l01);
                split2(c[mt][j][2], h10, l10);
                split2(c[mt][j][3], h11, l11);
                *reinterpret_cast<__nv_bfloat162*>(&outh[(size_t)row0 * N + col])       = __nv_bfloat162(h00, h01);
                *reinterpret_cast<__nv_bfloat162*>(&outh[(size_t)(row0 + 8) * N + col]) = __nv_bfloat162(h10, h11);
                *reinterpret_cast<__nv_bfloat162*>(&outl[(size_t)row0 * N + col])       = __nv_bfloat162(l00, l01);
                *reinterpret_cast<__nv_bfloat162*>(&outl[(size_t)(row0 + 8) * N + col]) = __nv_bfloat162(l10, l11);
            }
        }
    }
}

// ===========================================================================
// Final layer: y = H @ W2^T + b2
// ===========================================================================
__global__ void __launch_bounds__(256)
final_layer_kernel(const float* __restrict__ Hbuf, const float* __restrict__ W2,
                   const float* __restrict__ b2, float* __restrict__ y) {
    int b = blockIdx.x;
    const float4* hr = reinterpret_cast<const float4*>(Hbuf + (size_t)b * HH);

    float acc[DY];
#pragma unroll
    for (int d = 0; d < DY; d++) acc[d] = 0.0f;

    for (int i = threadIdx.x; i < HH / 4; i += 256) {
        float4 h4 = hr[i];
#pragma unroll
        for (int d = 0; d < DY; d++) {
            float4 w = *reinterpret_cast<const float4*>(&W2[(size_t)d * HH + i * 4]);
            acc[d] = fmaf(h4.x, w.x, acc[d]);
            acc[d] = fmaf(h4.y, w.y, acc[d]);
            acc[d] = fmaf(h4.z, w.z, acc[d]);
            acc[d] = fmaf(h4.w, w.w, acc[d]);
        }
    }

#pragma unroll
    for (int off = 16; off > 0; off >>= 1)
#pragma unroll
        for (int d = 0; d < DY; d++)
            acc[d] += __shfl_xor_sync(0xFFFFFFFFu, acc[d], off);

    __shared__ float red[8][DY];
    int w = threadIdx.x >> 5, l = threadIdx.x & 31;
    if (l == 0)
#pragma unroll
        for (int d = 0; d < DY; d++) red[w][d] = acc[d];
    __syncthreads();

    if (threadIdx.x < DY) {
        float s = b2[threadIdx.x];
#pragma unroll
        for (int ww = 0; ww < 8; ww++) s += red[ww][threadIdx.x];
        y[(size_t)b * DY + threadIdx.x] = s;
    }
}

// ===========================================================================
// Launch
// ===========================================================================
extern "C" void kernel_launch(void* const* d_in, const int* in_sizes, int n_in,
                              void* d_out, int out_size) {
    const float* x  = (const float*)d_in[0];
    const float* A  = (const float*)d_in[1];
    const float* W1 = (const float*)d_in[2];
    const float* b1 = (const float*)d_in[3];
    const float* W2 = (const float*)d_in[4];
    const float* b2 = (const float*)d_in[5];
    float* y = (float*)d_out;

    __nv_bfloat16* Sbuf;
    float* Hbuf;
    __nv_bfloat16 *xh, *xl, *w1h, *w1l, *wh, *wl;
    cudaGetSymbolAddress((void**)&Sbuf, g_S);
    cudaGetSymbolAddress((void**)&Hbuf, g_H);
    cudaGetSymbolAddress((void**)&xh, g_xh);
    cudaGetSymbolAddress((void**)&xl, g_xl);
    cudaGetSymbolAddress((void**)&w1h, g_w1h);
    cudaGetSymbolAddress((void**)&w1l, g_w1l);
    cudaGetSymbolAddress((void**)&wh, g_wh);
    cudaGetSymbolAddress((void**)&wl, g_wl);

    auto Sp = [&](int pp, int which) -> __nv_bfloat16* {
        return Sbuf + ((size_t)pp * 4 + which) * (DZ * DZ);
    };

    cudaFuncSetAttribute(mma_nt_kernel<0>,
                         cudaFuncAttributeMaxDynamicSharedMemorySize, MMA_SMEM);
    cudaFuncSetAttribute(mma_nt_kernel<1>,
                         cudaFuncAttributeMaxDynamicSharedMemorySize, MMA_SMEM);
    cudaFuncSetAttribute(square_mma_kernel,
                         cudaFuncAttributeMaxDynamicSharedMemorySize, SQ_SMEM);

    // 1) S = I + dt*A^T (bf16 hi/lo) and its transpose
    build_MT_kernel<<<dim3(DZ / 16, DZ / 16), dim3(16, 16)>>>(
        A, Sp(0, 0), Sp(0, 1), Sp(0, 2), Sp(0, 3), 1.0f / (float)NSTEPS);

    // independent splits
    split_kernel<<<(BB * DZ / 4 + 255) / 256, 256>>>(x, xh, xl, BB * DZ);
    split_kernel<<<(HH * DZ / 4 + 255) / 256, 256>>>(W1, w1h, w1l, HH * DZ);

    // 2) six squarings S <- S*S (bf16x3 tensor-core, epilogue re-split)
    int pp = 0;
    for (int s = 0; s < 6; ++s) {
        int np = pp ^ 1;
        square_mma_kernel<<<dim3(DZ / 64, DZ / 64), 128, SQ_SMEM>>>(
            Sp(pp, 0), Sp(pp, 1), Sp(pp, 2), Sp(pp, 3),
            Sp(np, 0), Sp(np, 1), Sp(np, 2), Sp(np, 3),
            (s < 5) ? 1 : 0);
        pp = np;
    }

    // 3) W1eff = W1 @ (M^64)^T  -> split epilogue into (wh, wl)
    mma_nt_kernel<1><<<dim3(DZ / BNN, HH / BMM), 256, MMA_SMEM>>>(
        w1h, w1l, Sp(pp, 0), Sp(pp, 1), nullptr, nullptr, wh, wl, DZ);

    // 4) H = relu(x @ W1eff^T + b1)
    mma_nt_kernel<0><<<dim3(HH / BNN, BB / BMM), 256, MMA_SMEM>>>(
        xh, xl, wh, wl, b1, Hbuf, nullptr, nullptr, HH);

    // 5) y = H @ W2^T + b2
    final_layer_kernel<<<BB, 256>>>(Hbuf, W2, b2, y);
}

// round 7
// speedup vs baseline: 2.4890x; 1.1128x over previous
#include <cuda_runtime.h>
#include <cuda_bf16.h>
#include <cstdint>

// Problem constants (fixed by the dataset)
#define BB   4096
#define DZ   512
#define HH   2048
#define DY   10
#define NSTEPS 64
#define KS   4          // split-K factor for squarings

// Scratch (allocation-free rule: __device__ globals)
// S state: [pingpong][ Sh | Sl | STh | STl ], each DZ*DZ bf16
__device__ __nv_bfloat16 g_S[2][4][DZ * DZ];
__device__ float g_Part[KS * DZ * DZ];
__device__ float g_H[(size_t)BB * HH];
__device__ __nv_bfloat16 g_xh[(size_t)BB * DZ];
__device__ __nv_bfloat16 g_xl[(size_t)BB * DZ];
__device__ __nv_bfloat16 g_w1h[(size_t)HH * DZ];
__device__ __nv_bfloat16 g_w1l[(size_t)HH * DZ];
__device__ __nv_bfloat16 g_wh[(size_t)HH * DZ];
__device__ __nv_bfloat16 g_wl[(size_t)HH * DZ];

// ===========================================================================
// helpers (base-arch instructions only)
// ===========================================================================
__device__ __forceinline__ uint32_t smem_u32(const void* p) {
    uint32_t a;
    asm("{ .reg .u64 t; cvta.to.shared.u64 t, %1; cvt.u32.u64 %0, t; }"
        : "=r"(a) : "l"(p));
    return a;
}
__device__ __forceinline__ void cpasync16(uint32_t dst, const void* src) {
    asm volatile("cp.async.cg.shared.global [%0], [%1], 16;" :: "r"(dst), "l"(src));
}
#define CP_COMMIT() asm volatile("cp.async.commit_group;" ::: "memory")
#define CP_WAIT(n)  asm volatile("cp.async.wait_group %0;" :: "n"(n) : "memory")

__device__ __forceinline__ void ldmx4(uint32_t* r, uint32_t addr) {
    asm volatile("ldmatrix.sync.aligned.m8n8.x4.shared.b16 {%0,%1,%2,%3}, [%4];"
                 : "=r"(r[0]), "=r"(r[1]), "=r"(r[2]), "=r"(r[3]) : "r"(addr));
}
__device__ __forceinline__ void mma16816(float* d, const uint32_t* a, const uint32_t* b) {
    asm volatile(
        "mma.sync.aligned.m16n8k16.row.col.f32.bf16.bf16.f32 "
        "{%0,%1,%2,%3}, {%4,%5,%6,%7}, {%8,%9}, {%0,%1,%2,%3};"
        : "+f"(d[0]), "+f"(d[1]), "+f"(d[2]), "+f"(d[3])
        : "r"(a[0]), "r"(a[1]), "r"(a[2]), "r"(a[3]), "r"(b[0]), "r"(b[1]));
}
__device__ __forceinline__ void split2(float v, __nv_bfloat16& h, __nv_bfloat16& l) {
    h = __float2bfloat16(v);
    l = __float2bfloat16(v - __bfloat162float(h));
}

// ===========================================================================
// build S = I + dt*A^T as bf16 hi/lo, plus transposed copies
// ===========================================================================
__global__ void __launch_bounds__(256)
build_MT_kernel(const float* __restrict__ A,
                __nv_bfloat16* __restrict__ Sh, __nv_bfloat16* __restrict__ Sl,
                __nv_bfloat16* __restrict__ STh, __nv_bfloat16* __restrict__ STl,
                float dt) {
    __shared__ float tile[16][17];
    int tx = threadIdx.x, ty = threadIdx.y;
    int i0 = blockIdx.x * 16, j0 = blockIdx.y * 16;
    int i = i0 + tx, j = j0 + ty;
    float v = dt * A[(size_t)j * DZ + i];
    if (i == j) v += 1.0f;
    __nv_bfloat16 h, l;
    split2(v, h, l);
    STh[(size_t)j * DZ + i] = h;
    STl[(size_t)j * DZ + i] = l;
    tile[ty][tx] = v;
    __syncthreads();
    float w = tile[tx][ty];
    split2(w, h, l);
    Sh[(size_t)(i0 + ty) * DZ + j0 + tx] = h;
    Sl[(size_t)(i0 + ty) * DZ + j0 + tx] = l;
}

// ===========================================================================
// bf16 hi/lo split of an fp32 array
// ===========================================================================
__global__ void __launch_bounds__(256)
split_kernel(const float* __restrict__ src, __nv_bfloat16* __restrict__ hi,
             __nv_bfloat16* __restrict__ lo, int n) {
    int i = (blockIdx.x * blockDim.x + threadIdx.x) * 4;
    if (i < n) {
        float4 v = *reinterpret_cast<const float4*>(&src[i]);
        __nv_bfloat16 h0, h1, h2, h3, l0, l1, l2, l3;
        split2(v.x, h0, l0); split2(v.y, h1, l1);
        split2(v.z, h2, l2); split2(v.w, h3, l3);
        *reinterpret_cast<__nv_bfloat162*>(&hi[i])     = __nv_bfloat162(h0, h1);
        *reinterpret_cast<__nv_bfloat162*>(&hi[i + 2]) = __nv_bfloat162(h2, h3);
        *reinterpret_cast<__nv_bfloat162*>(&lo[i])     = __nv_bfloat162(l0, l1);
        *reinterpret_cast<__nv_bfloat162*>(&lo[i + 2]) = __nv_bfloat162(l2, l3);
    }
}

// ===========================================================================
// Split-K squaring GEMM: Part[z] = S @ S over K slice z (bf16x3, NT form).
// 64x64 tile, BK=32, K-slice 128 (4 iters), 3-stage cp.async pipeline.
// ===========================================================================
#define SQ_PITCH 40
#define SQ_TSZ (64 * SQ_PITCH)
#define SQ_SMEM (3 * 4 * SQ_TSZ * 2)            // 61440 bytes

__global__ void __launch_bounds__(128, 1)
square_mma_kernel(const __nv_bfloat16* __restrict__ Ah, const __nv_bfloat16* __restrict__ Al,
                  const __nv_bfloat16* __restrict__ Bh, const __nv_bfloat16* __restrict__ Bl,
                  float* __restrict__ Part) {
    extern __shared__ __nv_bfloat16 sm[];
    const int tid  = threadIdx.x;
    const int wid  = tid >> 5;
    const int lane = tid & 31;
    const int bn0  = blockIdx.x * 64;
    const int bm0  = blockIdx.y * 64;
    const int kbeg = blockIdx.z * (DZ / KS);
    const int kend = kbeg + DZ / KS;
    float* out = Part + (size_t)blockIdx.z * DZ * DZ;
    const uint32_t sbase = smem_u32(sm);

    const int warp_m = wid >> 1;
    const int warp_n = wid & 1;
    const int m_base = warp_m * 32;
    const int n_base = warp_n * 32;

    auto stage = [&](int buf, int k0) {
        if (k0 < kend) {
            const __nv_bfloat16* srcs[4] = {Ah + (size_t)bm0 * DZ, Al + (size_t)bm0 * DZ,
                                            Bh + (size_t)bn0 * DZ, Bl + (size_t)bn0 * DZ};
            uint32_t bb = sbase + (uint32_t)buf * 4 * SQ_TSZ * 2;
#pragma unroll
            for (int tile = 0; tile < 4; ++tile) {
                uint32_t tb = bb + tile * SQ_TSZ * 2;
#pragma unroll
                for (int t = 0; t < 2; ++t) {
                    int idx = tid + t * 128;
                    int row = idx >> 2, c16 = idx & 3;
                    cpasync16(tb + (uint32_t)(row * SQ_PITCH + c16 * 8) * 2,
                              srcs[tile] + (size_t)row * DZ + k0 + c16 * 8);
                }
            }
        }
        CP_COMMIT();
    };

    float c[2][4][4];
#pragma unroll
    for (int mt = 0; mt < 2; mt++)
#pragma unroll
        for (int j = 0; j < 4; j++)
#pragma unroll
            for (int q = 0; q < 4; q++) c[mt][j][q] = 0.0f;

    stage(0, kbeg);
    stage(1, kbeg + 32);

    const int NIT = (DZ / KS) / 32;   // 4
    for (int it = 0; it < NIT; ++it) {
        stage((it + 2) % 3, kbeg + (it + 2) * 32);
        CP_WAIT(2);
        __syncthreads();

        uint32_t bb = sbase + (uint32_t)(it % 3) * 4 * SQ_TSZ * 2;
        uint32_t Ah_b = bb, Al_b = bb + SQ_TSZ * 2, Bh_b = bb + 2 * SQ_TSZ * 2,
                 Bl_b = bb + 3 * SQ_TSZ * 2;

#pragma unroll
        for (int ks = 0; ks < 2; ++ks) {
            int kc = ks * 16;
            uint32_t ah[2][4], al[2][4];
#pragma unroll
            for (int mt = 0; mt < 2; ++mt) {
                uint32_t roff = (uint32_t)((m_base + mt * 16 + (lane & 15)) * SQ_PITCH
                                           + kc + ((lane >> 4) << 3)) * 2;
                ldmx4(ah[mt], Ah_b + roff);
                ldmx4(al[mt], Al_b + roff);
            }
#pragma unroll
            for (int jp = 0; jp < 2; ++jp) {
                int n0 = n_base + jp * 16;
                uint32_t roff = (uint32_t)((n0 + (lane & 7) + ((lane >> 4) << 3)) * SQ_PITCH
                                           + kc + (((lane >> 3) & 1) << 3)) * 2;
                uint32_t bh[4], bl[4];
                ldmx4(bh, Bh_b + roff);
                ldmx4(bl, Bl_b + roff);
#pragma unroll
                for (int mt = 0; mt < 2; ++mt) {
                    mma16816(c[mt][2 * jp + 0], ah[mt], bh + 0);
                    mma16816(c[mt][2 * jp + 0], ah[mt], bl + 0);
                    mma16816(c[mt][2 * jp + 0], al[mt], bh + 0);
                    mma16816(c[mt][2 * jp + 1], ah[mt], bh + 2);
                    mma16816(c[mt][2 * jp + 1], ah[mt], bl + 2);
                    mma16816(c[mt][2 * jp + 1], al[mt], bh + 2);
                }
            }
        }
        __syncthreads();
    }

    // write fp32 partials
    const int g  = lane >> 2;
    const int t4 = lane & 3;
#pragma unroll
    for (int mt = 0; mt < 2; ++mt) {
        int r0 = bm0 + m_base + mt * 16 + g;
#pragma unroll
        for (int j = 0; j < 4; ++j) {
            int col = bn0 + n_base + j * 8 + t4 * 2;
            *reinterpret_cast<float2*>(&out[(size_t)r0 * DZ + col]) =
                make_float2(c[mt][j][0], c[mt][j][1]);
            *reinterpret_cast<float2*>(&out[(size_t)(r0 + 8) * DZ + col]) =
                make_float2(c[mt][j][2], c[mt][j][3]);
        }
    }
}

// ===========================================================================
// Fused reduce (KS partials, fixed order) -> hi/lo split -> C and C^T
// Grid (DZ/32, DZ/32), block (32, 8); smem transpose tile.
// ===========================================================================
__global__ void __launch_bounds__(256)
reduce_split_t_kernel(const float* __restrict__ P,
                      __nv_bfloat16* __restrict__ Ch, __nv_bfloat16* __restrict__ Cl,
                      __nv_bfloat16* __restrict__ CTh, __nv_bfloat16* __restrict__ CTl,
                      int write_t) {
    __shared__ float tile[32][33];
    const int tx = threadIdx.x, ty = threadIdx.y;
    const int r0 = blockIdx.y * 32, c0 = blockIdx.x * 32;
    const int n = DZ * DZ;

#pragma unroll
    for (int i = 0; i < 4; ++i) {
        int r = ty + 8 * i;
        size_t idx = (size_t)(r0 + r) * DZ + c0 + tx;
        float s = (P[idx] + P[idx + n]) + (P[idx + 2 * (size_t)n] + P[idx + 3 * (size_t)n]);
        tile[r][tx] = s;
        __nv_bfloat16 h, l;
        split2(s, h, l);
        Ch[idx] = h;
        Cl[idx] = l;
    }
    if (write_t) {
        __syncthreads();
#pragma unroll
        for (int i = 0; i < 4; ++i) {
            int cc = ty + 8 * i;
            float s = tile[tx][cc];
            __nv_bfloat16 h, l;
            split2(s, h, l);
            size_t tidx = (size_t)(c0 + cc) * DZ + r0 + tx;
            CTh[tidx] = h;
            CTl[tidx] = l;
        }
    }
}

// ===========================================================================
// Unified 128x128 NT mma kernel, bf16x3, 3-stage cp.async pipeline.
// EPI 0: out = relu(C + bias) as fp32 (main MLP layer)
// EPI 1: out = hi/lo bf16 split of C (W1eff production)
// ===========================================================================
#define BMM 128
#define BNN 128
#define PITCH 40
#define TSZ (BMM * PITCH)
#define MMA_SMEM (3 * 4 * TSZ * 2)              // 122880 bytes

template <int EPI>
__global__ void __launch_bounds__(256, 1)
mma_nt_kernel(const __nv_bfloat16* __restrict__ Amh, const __nv_bfloat16* __restrict__ Aml,
              const __nv_bfloat16* __restrict__ Bmh, const __nv_bfloat16* __restrict__ Bml,
              const float* __restrict__ bias, float* __restrict__ outf,
              __nv_bfloat16* __restrict__ outh, __nv_bfloat16* __restrict__ outl,
              int N) {
    extern __shared__ __nv_bfloat16 sm[];
    const int tid  = threadIdx.x;
    const int wid  = tid >> 5;
    const int lane = tid & 31;
    const int bn0  = blockIdx.x * BNN;
    const int bm0  = blockIdx.y * BMM;
    const uint32_t sbase = smem_u32(sm);

    const int warp_m = wid >> 1;
    const int warp_n = wid & 1;
    const int m_base = warp_m * 32;
    const int n_base = warp_n * 64;

    auto stage = [&](int buf, int k0) {
        if (k0 < DZ) {
            const __nv_bfloat16* srcs[4] = {Amh + (size_t)bm0 * DZ, Aml + (size_t)bm0 * DZ,
                                            Bmh + (size_t)bn0 * DZ, Bml + (size_t)bn0 * DZ};
            uint32_t bb = sbase + (uint32_t)buf * 4 * TSZ * 2;
#pragma unroll
            for (int tile = 0; tile < 4; ++tile) {
                uint32_t tb = bb + tile * TSZ * 2;
#pragma unroll
                for (int t = 0; t < 2; ++t) {
                    int idx = tid + t * 256;
                    int row = idx >> 2, c16 = idx & 3;
                    cpasync16(tb + (uint32_t)(row * PITCH + c16 * 8) * 2,
                              srcs[tile] + (size_t)row * DZ + k0 + c16 * 8);
                }
            }
        }
        CP_COMMIT();
    };

    float c[2][8][4];
#pragma unroll
    for (int mt = 0; mt < 2; mt++)
#pragma unroll
        for (int j = 0; j < 8; j++)
#pragma unroll
            for (int q = 0; q < 4; q++) c[mt][j][q] = 0.0f;

    stage(0, 0);
    stage(1, 32);

    const int NIT = DZ / 32;   // 16
    for (int it = 0; it < NIT; ++it) {
        stage((it + 2) % 3, (it + 2) * 32);
        CP_WAIT(2);
        __syncthreads();

        uint32_t bb = sbase + (uint32_t)(it % 3) * 4 * TSZ * 2;
        uint32_t Ah_b = bb, Al_b = bb + TSZ * 2, Bh_b = bb + 2 * TSZ * 2, Bl_b = bb + 3 * TSZ * 2;

#pragma unroll
        for (int ks = 0; ks < 2; ++ks) {
            int kc = ks * 16;
            uint32_t ah[2][4], al[2][4];
#pragma unroll
            for (int mt = 0; mt < 2; ++mt) {
                uint32_t roff = (uint32_t)((m_base + mt * 16 + (lane & 15)) * PITCH
                                           + kc + ((lane >> 4) << 3)) * 2;
                ldmx4(ah[mt], Ah_b + roff);
                ldmx4(al[mt], Al_b + roff);
            }
#pragma unroll
            for (int jp = 0; jp < 4; ++jp) {
                int n0 = n_base + jp * 16;
                uint32_t roff = (uint32_t)((n0 + (lane & 7) + ((lane >> 4) << 3)) * PITCH
                                           + kc + (((lane >> 3) & 1) << 3)) * 2;
                uint32_t bh[4], bl[4];
                ldmx4(bh, Bh_b + roff);
                ldmx4(bl, Bl_b + roff);
#pragma unroll
                for (int mt = 0; mt < 2; ++mt) {
                    mma16816(c[mt][2 * jp + 0], ah[mt], bh + 0);
                    mma16816(c[mt][2 * jp + 0], ah[mt], bl + 0);
                    mma16816(c[mt][2 * jp + 0], al[mt], bh + 0);
                    mma16816(c[mt][2 * jp + 1], ah[mt], bh + 2);
                    mma16816(c[mt][2 * jp + 1], ah[mt], bl + 2);
                    mma16816(c[mt][2 * jp + 1], al[mt], bh + 2);
                }
            }
        }
        __syncthreads();
    }

    const int g  = lane >> 2;
    const int t4 = lane & 3;
#pragma unroll
    for (int mt = 0; mt < 2; ++mt) {
        int row0 = bm0 + m_base + mt * 16 + g;
#pragma unroll
        for (int j = 0; j < 8; ++j) {
            int col = bn0 + n_base + j * 8 + t4 * 2;
            if (EPI == 0) {
                float bx = bias[col], by = bias[col + 1];
                float2 v0, v1;
                v0.x = fmaxf(c[mt][j][0] + bx, 0.0f);
                v0.y = fmaxf(c[mt][j][1] + by, 0.0f);
                v1.x = fmaxf(c[mt][j][2] + bx, 0.0f);
                v1.y = fmaxf(c[mt][j][3] + by, 0.0f);
                *reinterpret_cast<float2*>(&outf[(size_t)row0 * N + col])       = v0;
                *reinterpret_cast<float2*>(&outf[(size_t)(row0 + 8) * N + col]) = v1;
            } else {
                __nv_bfloat16 h00, l00, h01, l01, h10, l10, h11, l11;
                split2(c[mt][j][0], h00, l00);
                split2(c[mt][j][1], h01, l01);
                split2(c[mt][j][2], h10, l10);
                split2(c[mt][j][3], h11, l11);
                *reinterpret_cast<__nv_bfloat162*>(&outh[(size_t)row0 * N + col])       = __nv_bfloat162(h00, h01);
                *reinterpret_cast<__nv_bfloat162*>(&outh[(size_t)(row0 + 8) * N + col]) = __nv_bfloat162(h10, h11);
                *reinterpret_cast<__nv_bfloat162*>(&outl[(size_t)row0 * N + col])       = __nv_bfloat162(l00, l01);
                *reinterpret_cast<__nv_bfloat162*>(&outl[(size_t)(row0 + 8) * N + col]) = __nv_bfloat162(l10, l11);
            }
        }
    }
}

// ===========================================================================
// Final layer: y = H @ W2^T + b2.  H fp32. 4 batch rows per block.
// ===========================================================================
#define FLR 4
__global__ void __launch_bounds__(256)
final_layer_kernel(const float* __restrict__ Hf, const float* __restrict__ W2,
                   const float* __restrict__ b2, float* __restrict__ y) {
    const int b0 = blockIdx.x * FLR;
    const int i  = threadIdx.x;           // 0..255, each owns 8 h-columns

    float hf[FLR][8];
#pragma unroll
    for (int r = 0; r < FLR; ++r) {
        const float* hp = Hf + (size_t)(b0 + r) * HH + i * 8;
        float4 a = *reinterpret_cast<const float4*>(hp);
        float4 b = *reinterpret_cast<const float4*>(hp + 4);
        hf[r][0] = a.x; hf[r][1] = a.y; hf[r][2] = a.z; hf[r][3] = a.w;
        hf[r][4] = b.x; hf[r][5] = b.y; hf[r][6] = b.z; hf[r][7] = b.w;
    }

    float acc[FLR][DY];
#pragma unroll
    for (int r = 0; r < FLR; ++r)
#pragma unroll
        for (int d = 0; d < DY; ++d) acc[r][d] = 0.0f;

#pragma unroll
    for (int d = 0; d < DY; ++d) {
        float4 w0 = *reinterpret_cast<const float4*>(&W2[(size_t)d * HH + i * 8]);
        float4 w1 = *reinterpret_cast<const float4*>(&W2[(size_t)d * HH + i * 8 + 4]);
        float w[8] = {w0.x, w0.y, w0.z, w0.w, w1.x, w1.y, w1.z, w1.w};
#pragma unroll
        for (int r = 0; r < FLR; ++r)
#pragma unroll
            for (int k = 0; k < 8; ++k)
                acc[r][d] = fmaf(hf[r][k], w[k], acc[r][d]);
    }

    // warp reduction
#pragma unroll
    for (int off = 16; off > 0; off >>= 1)
#pragma unroll
        for (int r = 0; r < FLR; ++r)
#pragma unroll
            for (int d = 0; d < DY; ++d)
                acc[r][d] += __shfl_xor_sync(0xFFFFFFFFu, acc[r][d], off);

    __shared__ float red[8][FLR][DY];
    int w = threadIdx.x >> 5, l = threadIdx.x & 31;
    if (l == 0)
#pragma unroll
        for (int r = 0; r < FLR; ++r)
#pragma unroll
            for (int d = 0; d < DY; ++d) red[w][r][d] = acc[r][d];
    __syncthreads();

    if (threadIdx.x < FLR * DY) {
        int r = threadIdx.x / DY, d = threadIdx.x % DY;
        float s = b2[d];
#pragma unroll
        for (int ww = 0; ww < 8; ++ww) s += red[ww][r][d];
        y[(size_t)(b0 + r) * DY + d] = s;
    }
}

// ===========================================================================
// Launch
// ===========================================================================
extern "C" void kernel_launch(void* const* d_in, const int* in_sizes, int n_in,
                              void* d_out, int out_size) {
    const float* x  = (const float*)d_in[0];
    const float* A  = (const float*)d_in[1];
    const float* W1 = (const float*)d_in[2];
    const float* b1 = (const float*)d_in[3];
    const float* W2 = (const float*)d_in[4];
    const float* b2 = (const float*)d_in[5];
    float* y = (float*)d_out;

    __nv_bfloat16 *Sbuf, *xh, *xl, *w1h, *w1l, *wh, *wl;
    float *Part, *Hf;
    cudaGetSymbolAddress((void**)&Sbuf, g_S);
    cudaGetSymbolAddress((void**)&Part, g_Part);
    cudaGetSymbolAddress((void**)&Hf, g_H);
    cudaGetSymbolAddress((void**)&xh, g_xh);
    cudaGetSymbolAddress((void**)&xl, g_xl);
    cudaGetSymbolAddress((void**)&w1h, g_w1h);
    cudaGetSymbolAddress((void**)&w1l, g_w1l);
    cudaGetSymbolAddress((void**)&wh, g_wh);
    cudaGetSymbolAddress((void**)&wl, g_wl);

    auto Sp = [&](int pp, int which) -> __nv_bfloat16* {
        return Sbuf + ((size_t)pp * 4 + which) * (DZ * DZ);
    };

    cudaFuncSetAttribute(mma_nt_kernel<0>,
                         cudaFuncAttributeMaxDynamicSharedMemorySize, MMA_SMEM);
    cudaFuncSetAttribute(mma_nt_kernel<1>,
                         cudaFuncAttributeMaxDynamicSharedMemorySize, MMA_SMEM);
    cudaFuncSetAttribute(square_mma_kernel,
                         cudaFuncAttributeMaxDynamicSharedMemorySize, SQ_SMEM);

    // 1) S = I + dt*A^T (bf16 hi/lo) and its transpose
    build_MT_kernel<<<dim3(DZ / 16, DZ / 16), dim3(16, 16)>>>(
        A, Sp(0, 0), Sp(0, 1), Sp(0, 2), Sp(0, 3), 1.0f / (float)NSTEPS);

    // independent splits
    split_kernel<<<(BB * DZ / 4 + 255) / 256, 256>>>(x, xh, xl, BB * DZ);
    split_kernel<<<(HH * DZ / 4 + 255) / 256, 256>>>(W1, w1h, w1l, HH * DZ);

    // 2) six squarings S <- S*S : split-K gemm + fused reduce/split/transpose
    int pp = 0;
    for (int s = 0; s < 6; ++s) {
        int np = pp ^ 1;
        square_mma_kernel<<<dim3(DZ / 64, DZ / 64, KS), 128, SQ_SMEM>>>(
            Sp(pp, 0), Sp(pp, 1), Sp(pp, 2), Sp(pp, 3), Part);
        reduce_split_t_kernel<<<dim3(DZ / 32, DZ / 32), dim3(32, 8)>>>(
            Part, Sp(np, 0), Sp(np, 1), Sp(np, 2), Sp(np, 3), (s < 5) ? 1 : 0);
        pp = np;
    }

    // 3) W1eff = W1 @ (M^64)^T  -> split epilogue into (wh, wl)
    mma_nt_kernel<1><<<dim3(DZ / BNN, HH / BMM), 256, MMA_SMEM>>>(
        w1h, w1l, Sp(pp, 0), Sp(pp, 1), nullptr, nullptr, wh, wl, DZ);

    // 4) H = relu(x @ W1eff^T + b1), fp32 output
    mma_nt_kernel<0><<<dim3(HH / BNN, BB / BMM), 256, MMA_SMEM>>>(
        xh, xl, wh, wl, b1, Hf, nullptr, nullptr, HH);

    // 5) y = H @ W2^T + b2
    final_layer_kernel<<<BB / FLR, 256>>>(Hf, W2, b2, y);
}